// round 1
// baseline (speedup 1.0000x reference)
#include <cuda_runtime.h>
#include <cuda_bf16.h>

// Problem constants (fixed by the dataset's reference_code)
#define HW_DIM     512
#define NB         6
#define NLOOPS     4
#define NDET       4096
#define NSAMP      128
#define NPTS       (NDET * NSAMP)          // 524288
#define CH_STRIDE  (512 * 512)             // per-channel elements
#define B_STRIDE   (2 * NB * 512 * 512)    // per-batch elements (12 channels)

__global__ void __launch_bounds__(256)
refine_kernel(const float*  __restrict__ det_in,     // [NDET, NSAMP, 2]
              const float*  __restrict__ refinement, // [BATCH, 12, 512, 512]
              const float*  __restrict__ sampling,   // [NSAMP]
              const int*    __restrict__ bvec,       // [NDET]
              float*        __restrict__ out)        // [NDET, NSAMP, 2]
{
    int t = blockIdx.x * blockDim.x + threadIdx.x;
    if (t >= NPTS) return;

    const int s = t & (NSAMP - 1);
    const int d = t >> 7;

    // Per-sample bucket setup — reproduce reference arithmetic exactly.
    // base = sampling*NB; base_int = floor(base).
    // off=-1 tap has weight 1-|base-(base_int-1)| <= 0 always -> skipped.
    const float base  = sampling[s] * (float)NB;
    const float bif   = floorf(base);
    const int   bint  = (int)bif;

    // w0: off=0 -> d0 = |bif - base| = base - bif (<1 always)
    const float d0 = fabsf(bif - base);
    const float w0 = (d0 > 1.0f) ? 0.0f : (1.0f - d0);
    // w1: off=+1 -> d1 = |(bif+1) - base|
    const float d1 = fabsf((bif + 1.0f) - base);
    const float w1 = (d1 > 1.0f) ? 0.0f : (1.0f - d1);

    const int c0 = (bint % NB) * 2;           // bint in [0,5]
    const int c1 = (((bint + 1) % NB)) * 2;   // wraps 6 -> 0

    const float* __restrict__ refb = refinement + (long)bvec[d] * B_STRIDE;
    const float* __restrict__ p0   = refb + (long)c0 * CH_STRIDE;
    const float* __restrict__ p1   = refb + (long)c1 * CH_STRIDE;

    float2 det = reinterpret_cast<const float2*>(det_in)[t];
    float x = det.x, y = det.y;

    #pragma unroll
    for (int l = 0; l < NLOOPS; ++l) {
        // round-half-even (matches jnp.round), then clip
        float xr = rintf(x);
        float yr = rintf(y);
        xr = fminf(fmaxf(xr, 0.0f), (float)(HW_DIM - 1));
        yr = fminf(fmaxf(yr, 0.0f), (float)(HW_DIM - 1));
        const int xi  = (int)xr;
        const int yi  = (int)yr;
        const int pix = yi * HW_DIM + xi;

        // 4 independent gathers (L2 hits after warmup) — issue together
        const float r0x = __ldg(p0 + pix);
        const float r0y = __ldg(p0 + CH_STRIDE + pix);
        const float r1x = __ldg(p1 + pix);
        const float r1y = __ldg(p1 + CH_STRIDE + pix);

        x = xr + (w0 * r0x + w1 * r1x);
        y = yr + (w0 * r0y + w1 * r1y);
    }

    reinterpret_cast<float2*>(out)[t] = make_float2(x, y);
}

extern "C" void kernel_launch(void* const* d_in, const int* in_sizes, int n_in,
                              void* d_out, int out_size)
{
    // Identify inputs by element count (robust to metadata ordering):
    //   det_indices : 4096*128*2 = 1048576 f32
    //   refinement  : 4*12*512*512 = 12582912 f32
    //   sampling    : 128 f32
    //   b           : 4096 i32
    const float* det_in     = nullptr;
    const float* refinement = nullptr;
    const float* sampling   = nullptr;
    const int*   bvec       = nullptr;

    for (int i = 0; i < n_in; ++i) {
        switch (in_sizes[i]) {
            case 1048576:  det_in     = (const float*)d_in[i]; break;
            case 12582912: refinement = (const float*)d_in[i]; break;
            case 128:      sampling   = (const float*)d_in[i]; break;
            case 4096:     bvec       = (const int*)d_in[i];   break;
            default: break; // scalar params (num_loops etc.) — constants baked in
        }
    }

    const int threads = 256;
    const int blocks  = (NPTS + threads - 1) / threads;
    refine_kernel<<<blocks, threads>>>(det_in, refinement, sampling, bvec,
                                       (float*)d_out);
}